// round 11
// baseline (speedup 1.0000x reference)
#include <cuda_runtime.h>

#define NT 128

// ---------------------------------------------------------------------------
// Packed f32x2 FMA (Blackwell sm_100+/103a). One instruction = 2 fp32 FMAs.
// ---------------------------------------------------------------------------
union F2U { float2 f; unsigned long long u; };

__device__ __forceinline__ float2 f2fma(float2 a, float2 b, float2 c) {
    F2U ua, ub, uc, ud;
    ua.f = a; ub.f = b; uc.f = c;
    asm("fma.rn.f32x2 %0, %1, %2, %3;" : "=l"(ud.u) : "l"(ua.u), "l"(ub.u), "l"(uc.u));
    return ud.f;
}

// ---------------------------------------------------------------------------
// Shared-memory weight cache: all MLP weights packed as float2 pairs.
// Wout / bout (9 outputs) padded to 5 pairs with a zero in the last slot.
// Plus per-thread CPAB knot scratch V[11][NT] (tid-major -> conflict-free
// even with divergent per-lane cell indices).
// Total ~41.7 KB static shared (< 48 KB static limit).
// ---------------------------------------------------------------------------
struct Smem {
    float2 W0[15][15][5];
    float2 B0[15][5];
    float2 WH[15][3][10][5];
    float2 BH[15][3][5];
    float2 WO[15][10][5];
    float2 BO[15][5];
    float  IP[9];
    float  V[11][NT];
};

// ---------------------------------------------------------------------------
// One CPAB transform: exact mirror of the JAX scan (Nc=10, 11 steps, fp32,
// select-based; precise logf/expf). vb points at this thread's column of
// sm.V: v[k] lives at vb[k*NT].
// ---------------------------------------------------------------------------
__device__ __forceinline__ void cpab1(float x0, const float* __restrict__ vb,
                                      float& zf, float& lf)
{
    const float INF = __int_as_float(0x7f800000);
    float xc = x0, t = 1.0f, ld = 0.0f;
    #pragma unroll
    for (int s = 0; s < 11; ++s) {
        float cf = floorf(xc * 10.0f);
        int c = (int)cf;
        c = c < 0 ? 0 : (c > 9 ? 9 : c);
        float fc  = (float)c;
        float vc  = vb[c * NT];
        float vc1 = vb[(c + 1) * NT];
        float ac  = (vc1 - vc) * 10.0f;
        float bc  = vc - ac * (fc * 0.1f);
        float vel = ac * xc + bc;
        float xb  = (vel >= 0.0f) ? (fc + 1.0f) * 0.1f : fc * 0.1f;
        float vbn = ac * xb + bc;
        bool  small    = fabsf(ac) < 1e-8f;
        float vel_safe = (vel == 0.0f) ? 1.0f : vel;
        float ac_safe  = small ? 1.0f : ac;
        float dt_lin   = (xb - xc) / vel_safe;
        float ratio    = fmaxf(vbn / vel_safe, 1e-38f);
        float dt_exp   = logf(ratio) / ac_safe;
        float dt_hit   = small ? dt_lin : dt_exp;
        dt_hit = (vel == 0.0f || dt_hit < 0.0f) ? INF : dt_hit;
        float dt    = fminf(t, dt_hit);
        float x_lin = xc + vel * dt;
        float boa   = bc / ac_safe;
        float x_exp = (xc + boa) * expf(ac * dt) - boa;
        float x_new = small ? x_lin : x_exp;
        bool  hit   = dt_hit <= t;
        x_new = hit ? (xb + ((vel >= 0.0f) ? 1e-8f : -1e-8f)) : x_new;
        xc = fminf(fmaxf(x_new, 0.0f), 1.0f);
        t  = fmaxf(t - dt, 0.0f);
        ld += ac * dt;
    }
    zf = xc; lf = ld;
}

__global__ void __launch_bounds__(NT)
cpab_ar_kernel(const float* __restrict__ x,
               const float* __restrict__ ip,
               const float* __restrict__ W0,
               const float* __restrict__ b0,
               const float* __restrict__ Wh,
               const float* __restrict__ bh,
               const float* __restrict__ Wo,
               const float* __restrict__ bo,
               float* __restrict__ out,
               int B)
{
    __shared__ Smem sm;
    const int tid = threadIdx.x;

    // ---- cooperative fill of packed weight cache ----
    for (int idx = tid; idx < 15 * 15 * 5; idx += NT) {
        int i = idx / 75, r = idx % 75, j = r / 5, p = r % 5;
        const float* s = W0 + (i * 15 + j) * 10 + 2 * p;
        sm.W0[i][j][p] = make_float2(s[0], s[1]);
    }
    for (int idx = tid; idx < 15 * 5; idx += NT) {
        int i = idx / 5, p = idx % 5;
        const float* s = b0 + i * 10 + 2 * p;
        sm.B0[i][p] = make_float2(s[0], s[1]);
    }
    for (int idx = tid; idx < 15 * 3 * 10 * 5; idx += NT) {
        int i = idx / 150, r = idx % 150, l = r / 50, r2 = r % 50, j = r2 / 5, p = r2 % 5;
        const float* s = Wh + ((i * 3 + l) * 10 + j) * 10 + 2 * p;
        sm.WH[i][l][j][p] = make_float2(s[0], s[1]);
    }
    for (int idx = tid; idx < 15 * 3 * 5; idx += NT) {
        int i = idx / 15, r = idx % 15, l = r / 5, p = r % 5;
        const float* s = bh + (i * 3 + l) * 10 + 2 * p;
        sm.BH[i][l][p] = make_float2(s[0], s[1]);
    }
    for (int idx = tid; idx < 15 * 10 * 5; idx += NT) {
        int i = idx / 50, r = idx % 50, j = r / 5, p = r % 5;
        const float* s = Wo + (i * 10 + j) * 9;
        sm.WO[i][j][p] = (p < 4) ? make_float2(s[2 * p], s[2 * p + 1])
                                 : make_float2(s[8], 0.0f);
    }
    for (int idx = tid; idx < 15 * 5; idx += NT) {
        int i = idx / 5, p = idx % 5;
        const float* s = bo + i * 9;
        sm.BO[i][p] = (p < 4) ? make_float2(s[2 * p], s[2 * p + 1])
                              : make_float2(s[8], 0.0f);
    }
    if (tid < 9) sm.IP[tid] = ip[tid];
    __syncthreads();

    const int n = blockIdx.x * NT + tid;
    if (n >= B) return;

    // ---- load + clip x (vectorized) ----
    float xr[16];
    {
        const float4* xg = reinterpret_cast<const float4*>(x + (size_t)n * 16);
        float4 v0 = xg[0], v1 = xg[1], v2 = xg[2], v3 = xg[3];
        float tmp[16] = { v0.x, v0.y, v0.z, v0.w,  v1.x, v1.y, v1.z, v1.w,
                          v2.x, v2.y, v2.z, v2.w,  v3.x, v3.y, v3.z, v3.w };
        const float lo = 1e-7f;
        const float hi = 1.0f - 1e-7f;
        #pragma unroll
        for (int k = 0; k < 16; ++k) xr[k] = fminf(fmaxf(tmp[k], lo), hi);
    }

    float zo[16], lo_[16];
    float* vb = &sm.V[0][tid];

    // ---- d = 0 transform: shared init_param ----
    vb[0] = 0.0f;
    #pragma unroll
    for (int k = 0; k < 9; ++k) vb[(k + 1) * NT] = sm.IP[k];
    vb[10 * NT] = 0.0f;
    cpab1(xr[0], vb, zo[0], lo_[0]);

    // ---- heads i = 0..14: MLP_i(x[0..i]) -> theta -> transform on x[i+1] ----
    for (int i = 0; i < 15; ++i) {
        float2 h[5];
        #pragma unroll
        for (int p = 0; p < 5; ++p) h[p] = sm.B0[i][p];

        // layer 0 (masked: only inputs 0..i contribute)
        for (int j = 0; j <= i; ++j) {
            float xv = xr[j];
            float2 xp = make_float2(xv, xv);
            #pragma unroll
            for (int p = 0; p < 5; ++p) h[p] = f2fma(xp, sm.W0[i][j][p], h[p]);
        }

        // 3 hidden layers with ReLU
        #pragma unroll
        for (int l = 0; l < 3; ++l) {
            float hs[10];
            #pragma unroll
            for (int p = 0; p < 5; ++p) { hs[2 * p] = h[p].x; hs[2 * p + 1] = h[p].y; }
            float2 g[5];
            #pragma unroll
            for (int p = 0; p < 5; ++p) g[p] = sm.BH[i][l][p];
            #pragma unroll
            for (int j = 0; j < 10; ++j) {
                float2 hp = make_float2(hs[j], hs[j]);
                #pragma unroll
                for (int p = 0; p < 5; ++p) g[p] = f2fma(hp, sm.WH[i][l][j][p], g[p]);
            }
            #pragma unroll
            for (int p = 0; p < 5; ++p) {
                h[p].x = fmaxf(g[p].x, 0.0f);
                h[p].y = fmaxf(g[p].y, 0.0f);
            }
        }

        // output layer (9 outputs, padded to 5 pairs)
        float hs[10];
        #pragma unroll
        for (int p = 0; p < 5; ++p) { hs[2 * p] = h[p].x; hs[2 * p + 1] = h[p].y; }
        float2 o[5];
        #pragma unroll
        for (int p = 0; p < 5; ++p) o[p] = sm.BO[i][p];
        #pragma unroll
        for (int j = 0; j < 10; ++j) {
            float2 hp = make_float2(hs[j], hs[j]);
            #pragma unroll
            for (int p = 0; p < 5; ++p) o[p] = f2fma(hp, sm.WO[i][j][p], o[p]);
        }

        // knot velocities v = [0, theta(9), 0]
        vb[0]      = 0.0f;
        vb[1 * NT] = o[0].x;  vb[2 * NT] = o[0].y;
        vb[3 * NT] = o[1].x;  vb[4 * NT] = o[1].y;
        vb[5 * NT] = o[2].x;  vb[6 * NT] = o[2].y;
        vb[7 * NT] = o[3].x;  vb[8 * NT] = o[3].y;
        vb[9 * NT] = o[4].x;
        vb[10 * NT] = 0.0f;

        cpab1(xr[i + 1], vb, zo[i + 1], lo_[i + 1]);
    }

    // ---- vectorized stores: z at [0, B*16), log-grad at [B*16, 2*B*16) ----
    float4* zg = reinterpret_cast<float4*>(out + (size_t)n * 16);
    float4* lg = reinterpret_cast<float4*>(out + (size_t)B * 16 + (size_t)n * 16);
    #pragma unroll
    for (int q = 0; q < 4; ++q) {
        zg[q] = make_float4(zo[4 * q], zo[4 * q + 1], zo[4 * q + 2], zo[4 * q + 3]);
        lg[q] = make_float4(lo_[4 * q], lo_[4 * q + 1], lo_[4 * q + 2], lo_[4 * q + 3]);
    }
}

extern "C" void kernel_launch(void* const* d_in, const int* in_sizes, int n_in,
                              void* d_out, int out_size)
{
    const float* x  = (const float*)d_in[0];
    const float* ip = (const float*)d_in[1];
    const float* W0 = (const float*)d_in[2];
    const float* b0 = (const float*)d_in[3];
    const float* Wh = (const float*)d_in[4];
    const float* bh = (const float*)d_in[5];
    const float* Wo = (const float*)d_in[6];
    const float* bo = (const float*)d_in[7];
    float* out = (float*)d_out;

    int B = in_sizes[0] / 16;
    int grid = (B + NT - 1) / NT;
    cpab_ar_kernel<<<grid, NT>>>(x, ip, W0, b0, Wh, bh, Wo, bo, out, B);
}

// round 12
// speedup vs baseline: 1.0004x; 1.0004x over previous
#include <cuda_runtime.h>

#define NT 128

// ---------------------------------------------------------------------------
// Packed f32x2 FMA (Blackwell sm_100+/103a). One instruction = 2 fp32 FMAs.
// ---------------------------------------------------------------------------
union F2U { float2 f; unsigned long long u; };

__device__ __forceinline__ float2 f2fma(float2 a, float2 b, float2 c) {
    F2U ua, ub, uc, ud;
    ua.f = a; ub.f = b; uc.f = c;
    asm("fma.rn.f32x2 %0, %1, %2, %3;" : "=l"(ud.u) : "l"(ua.u), "l"(ub.u), "l"(uc.u));
    return ud.f;
}

// ---------------------------------------------------------------------------
// Shared-memory weight cache: all MLP weights packed as float2 pairs.
// Wout / bout (9 outputs) padded to 5 pairs with a zero in the last slot.
// Plus per-thread CPAB knot scratch V[11][NT] (tid-major -> conflict-free
// even with divergent per-lane cell indices).
// Total ~41.7 KB static shared (< 48 KB static limit).
// ---------------------------------------------------------------------------
struct Smem {
    float2 W0[15][15][5];
    float2 B0[15][5];
    float2 WH[15][3][10][5];
    float2 BH[15][3][5];
    float2 WO[15][10][5];
    float2 BO[15][5];
    float  IP[9];
    float  V[11][NT];
};

// ---------------------------------------------------------------------------
// One CPAB transform: exact mirror of the JAX scan (Nc=10, 11 steps, fp32,
// select-based; precise logf/expf). vb points at this thread's column of
// sm.V: v[k] lives at vb[k*NT].
// ---------------------------------------------------------------------------
__device__ __forceinline__ void cpab1(float x0, const float* __restrict__ vb,
                                      float& zf, float& lf)
{
    const float INF = __int_as_float(0x7f800000);
    float xc = x0, t = 1.0f, ld = 0.0f;
    #pragma unroll
    for (int s = 0; s < 11; ++s) {
        float cf = floorf(xc * 10.0f);
        int c = (int)cf;
        c = c < 0 ? 0 : (c > 9 ? 9 : c);
        float fc  = (float)c;
        float vc  = vb[c * NT];
        float vc1 = vb[(c + 1) * NT];
        float ac  = (vc1 - vc) * 10.0f;
        float bc  = vc - ac * (fc * 0.1f);
        float vel = ac * xc + bc;
        float xb  = (vel >= 0.0f) ? (fc + 1.0f) * 0.1f : fc * 0.1f;
        float vbn = ac * xb + bc;
        bool  small    = fabsf(ac) < 1e-8f;
        float vel_safe = (vel == 0.0f) ? 1.0f : vel;
        float ac_safe  = small ? 1.0f : ac;
        float dt_lin   = (xb - xc) / vel_safe;
        float ratio    = fmaxf(vbn / vel_safe, 1e-38f);
        float dt_exp   = logf(ratio) / ac_safe;
        float dt_hit   = small ? dt_lin : dt_exp;
        dt_hit = (vel == 0.0f || dt_hit < 0.0f) ? INF : dt_hit;
        float dt    = fminf(t, dt_hit);
        float x_lin = xc + vel * dt;
        float boa   = bc / ac_safe;
        float x_exp = (xc + boa) * expf(ac * dt) - boa;
        float x_new = small ? x_lin : x_exp;
        bool  hit   = dt_hit <= t;
        x_new = hit ? (xb + ((vel >= 0.0f) ? 1e-8f : -1e-8f)) : x_new;
        xc = fminf(fmaxf(x_new, 0.0f), 1.0f);
        t  = fmaxf(t - dt, 0.0f);
        ld += ac * dt;
    }
    zf = xc; lf = ld;
}

__global__ void __launch_bounds__(NT)
cpab_ar_kernel(const float* __restrict__ x,
               const float* __restrict__ ip,
               const float* __restrict__ W0,
               const float* __restrict__ b0,
               const float* __restrict__ Wh,
               const float* __restrict__ bh,
               const float* __restrict__ Wo,
               const float* __restrict__ bo,
               float* __restrict__ out,
               int B)
{
    __shared__ Smem sm;
    const int tid = threadIdx.x;

    // ---- cooperative fill of packed weight cache ----
    for (int idx = tid; idx < 15 * 15 * 5; idx += NT) {
        int i = idx / 75, r = idx % 75, j = r / 5, p = r % 5;
        const float* s = W0 + (i * 15 + j) * 10 + 2 * p;
        sm.W0[i][j][p] = make_float2(s[0], s[1]);
    }
    for (int idx = tid; idx < 15 * 5; idx += NT) {
        int i = idx / 5, p = idx % 5;
        const float* s = b0 + i * 10 + 2 * p;
        sm.B0[i][p] = make_float2(s[0], s[1]);
    }
    for (int idx = tid; idx < 15 * 3 * 10 * 5; idx += NT) {
        int i = idx / 150, r = idx % 150, l = r / 50, r2 = r % 50, j = r2 / 5, p = r2 % 5;
        const float* s = Wh + ((i * 3 + l) * 10 + j) * 10 + 2 * p;
        sm.WH[i][l][j][p] = make_float2(s[0], s[1]);
    }
    for (int idx = tid; idx < 15 * 3 * 5; idx += NT) {
        int i = idx / 15, r = idx % 15, l = r / 5, p = r % 5;
        const float* s = bh + (i * 3 + l) * 10 + 2 * p;
        sm.BH[i][l][p] = make_float2(s[0], s[1]);
    }
    for (int idx = tid; idx < 15 * 10 * 5; idx += NT) {
        int i = idx / 50, r = idx % 50, j = r / 5, p = r % 5;
        const float* s = Wo + (i * 10 + j) * 9;
        sm.WO[i][j][p] = (p < 4) ? make_float2(s[2 * p], s[2 * p + 1])
                                 : make_float2(s[8], 0.0f);
    }
    for (int idx = tid; idx < 15 * 5; idx += NT) {
        int i = idx / 5, p = idx % 5;
        const float* s = bo + i * 9;
        sm.BO[i][p] = (p < 4) ? make_float2(s[2 * p], s[2 * p + 1])
                              : make_float2(s[8], 0.0f);
    }
    if (tid < 9) sm.IP[tid] = ip[tid];
    __syncthreads();

    const int n = blockIdx.x * NT + tid;
    if (n >= B) return;

    // ---- load + clip x (vectorized) ----
    float xr[16];
    {
        const float4* xg = reinterpret_cast<const float4*>(x + (size_t)n * 16);
        float4 v0 = xg[0], v1 = xg[1], v2 = xg[2], v3 = xg[3];
        float tmp[16] = { v0.x, v0.y, v0.z, v0.w,  v1.x, v1.y, v1.z, v1.w,
                          v2.x, v2.y, v2.z, v2.w,  v3.x, v3.y, v3.z, v3.w };
        const float lo = 1e-7f;
        const float hi = 1.0f - 1e-7f;
        #pragma unroll
        for (int k = 0; k < 16; ++k) xr[k] = fminf(fmaxf(tmp[k], lo), hi);
    }

    float zo[16], lo_[16];
    float* vb = &sm.V[0][tid];

    // ---- d = 0 transform: shared init_param ----
    vb[0] = 0.0f;
    #pragma unroll
    for (int k = 0; k < 9; ++k) vb[(k + 1) * NT] = sm.IP[k];
    vb[10 * NT] = 0.0f;
    cpab1(xr[0], vb, zo[0], lo_[0]);

    // ---- heads i = 0..14: MLP_i(x[0..i]) -> theta -> transform on x[i+1] ----
    for (int i = 0; i < 15; ++i) {
        float2 h[5];
        #pragma unroll
        for (int p = 0; p < 5; ++p) h[p] = sm.B0[i][p];

        // layer 0 (masked: only inputs 0..i contribute)
        for (int j = 0; j <= i; ++j) {
            float xv = xr[j];
            float2 xp = make_float2(xv, xv);
            #pragma unroll
            for (int p = 0; p < 5; ++p) h[p] = f2fma(xp, sm.W0[i][j][p], h[p]);
        }

        // 3 hidden layers with ReLU
        #pragma unroll
        for (int l = 0; l < 3; ++l) {
            float hs[10];
            #pragma unroll
            for (int p = 0; p < 5; ++p) { hs[2 * p] = h[p].x; hs[2 * p + 1] = h[p].y; }
            float2 g[5];
            #pragma unroll
            for (int p = 0; p < 5; ++p) g[p] = sm.BH[i][l][p];
            #pragma unroll
            for (int j = 0; j < 10; ++j) {
                float2 hp = make_float2(hs[j], hs[j]);
                #pragma unroll
                for (int p = 0; p < 5; ++p) g[p] = f2fma(hp, sm.WH[i][l][j][p], g[p]);
            }
            #pragma unroll
            for (int p = 0; p < 5; ++p) {
                h[p].x = fmaxf(g[p].x, 0.0f);
                h[p].y = fmaxf(g[p].y, 0.0f);
            }
        }

        // output layer (9 outputs, padded to 5 pairs)
        float hs[10];
        #pragma unroll
        for (int p = 0; p < 5; ++p) { hs[2 * p] = h[p].x; hs[2 * p + 1] = h[p].y; }
        float2 o[5];
        #pragma unroll
        for (int p = 0; p < 5; ++p) o[p] = sm.BO[i][p];
        #pragma unroll
        for (int j = 0; j < 10; ++j) {
            float2 hp = make_float2(hs[j], hs[j]);
            #pragma unroll
            for (int p = 0; p < 5; ++p) o[p] = f2fma(hp, sm.WO[i][j][p], o[p]);
        }

        // knot velocities v = [0, theta(9), 0]
        vb[0]      = 0.0f;
        vb[1 * NT] = o[0].x;  vb[2 * NT] = o[0].y;
        vb[3 * NT] = o[1].x;  vb[4 * NT] = o[1].y;
        vb[5 * NT] = o[2].x;  vb[6 * NT] = o[2].y;
        vb[7 * NT] = o[3].x;  vb[8 * NT] = o[3].y;
        vb[9 * NT] = o[4].x;
        vb[10 * NT] = 0.0f;

        cpab1(xr[i + 1], vb, zo[i + 1], lo_[i + 1]);
    }

    // ---- vectorized stores: z at [0, B*16), log-grad at [B*16, 2*B*16) ----
    float4* zg = reinterpret_cast<float4*>(out + (size_t)n * 16);
    float4* lg = reinterpret_cast<float4*>(out + (size_t)B * 16 + (size_t)n * 16);
    #pragma unroll
    for (int q = 0; q < 4; ++q) {
        zg[q] = make_float4(zo[4 * q], zo[4 * q + 1], zo[4 * q + 2], zo[4 * q + 3]);
        lg[q] = make_float4(lo_[4 * q], lo_[4 * q + 1], lo_[4 * q + 2], lo_[4 * q + 3]);
    }
}

extern "C" void kernel_launch(void* const* d_in, const int* in_sizes, int n_in,
                              void* d_out, int out_size)
{
    const float* x  = (const float*)d_in[0];
    const float* ip = (const float*)d_in[1];
    const float* W0 = (const float*)d_in[2];
    const float* b0 = (const float*)d_in[3];
    const float* Wh = (const float*)d_in[4];
    const float* bh = (const float*)d_in[5];
    const float* Wo = (const float*)d_in[6];
    const float* bo = (const float*)d_in[7];
    float* out = (float*)d_out;

    int B = in_sizes[0] / 16;
    int grid = (B + NT - 1) / NT;
    cpab_ar_kernel<<<grid, NT>>>(x, ip, W0, b0, Wh, bh, Wo, bo, out, B);
}

// round 17
// speedup vs baseline: 1.9695x; 1.9687x over previous
#include <cuda_runtime.h>

#define NT 128

// ---------------------------------------------------------------------------
// Packed f32x2 FMA (Blackwell sm_103a). One instruction = 2 fp32 FMAs.
// ---------------------------------------------------------------------------
union F2U { float2 f; unsigned long long u; };

__device__ __forceinline__ float2 f2fma(float2 a, float2 b, float2 c) {
    F2U ua, ub, uc, ud;
    ua.f = a; ub.f = b; uc.f = c;
    asm("fma.rn.f32x2 %0, %1, %2, %3;" : "=l"(ud.u) : "l"(ua.u), "l"(ub.u), "l"(uc.u));
    return ud.f;
}

__device__ __forceinline__ float frcp_fast(float x) {
    float r;
    asm("rcp.approx.f32 %0, %1;" : "=f"(r) : "f"(x));
    return r;
}

// ---------------------------------------------------------------------------
// Shared memory: MLP weights packed as float2 pairs (Wout padded 9 -> 5
// pairs), plus per-thread CPAB knot table V[11][NT] (tid-major ->
// conflict-free under divergent cell indices). ~41.7 KB -> 5 blocks/SM.
// ---------------------------------------------------------------------------
struct Smem {
    float2 W0[15][15][5];
    float2 B0[15][5];
    float2 WH[15][3][10][5];
    float2 BH[15][3][5];
    float2 WO[15][10][5];
    float2 BO[15][5];
    float  IP[9];
    float  V[11][NT];
};

// ---------------------------------------------------------------------------
// One CPAB transform (Nc=10, <=11 steps). The branch-deciding chain
// (vel/vbn/ratio via PRECISE div, PRECISE logf) is verbatim the proven R12
// kernel, so hit/INF decisions match the reference. Decision-independent
// pieces use fast ops:
//   * dt_exp scale, boa, dt_lin:  rcp.approx (sign-exact, 1.2e-7 rel)
//   * x_exp exponential:          __expf (applied after the decision)
// Early break when t==0: remaining reference steps are exact no-ops.
// __noinline__ + unroll 1: single code copy (I$-friendly) for 16 call sites.
// ---------------------------------------------------------------------------
__device__ __noinline__ float2 cpab1(float x0, const float* vb)
{
    const float INF = __int_as_float(0x7f800000);
    float xc = x0, t = 1.0f, ld = 0.0f;
    #pragma unroll 1
    for (int s = 0; s < 11; ++s) {
        float cf = floorf(xc * 10.0f);
        int c = (int)cf;
        c = c < 0 ? 0 : (c > 9 ? 9 : c);
        float fc  = (float)c;
        float vc  = vb[c * NT];
        float vc1 = vb[(c + 1) * NT];
        float ac  = (vc1 - vc) * 10.0f;
        float bc  = vc - ac * (fc * 0.1f);
        float vel = ac * xc + bc;
        float xb  = (vel >= 0.0f) ? (fc + 1.0f) * 0.1f : fc * 0.1f;
        float vbn = ac * xb + bc;

        bool  small    = fabsf(ac) < 1e-8f;
        float vel_safe = (vel == 0.0f) ? 1.0f : vel;
        float ac_safe  = small ? 1.0f : ac;
        float inv_a    = frcp_fast(ac_safe);

        float dt_lin = (xb - xc) * frcp_fast(vel_safe);
        float ratio  = fmaxf(vbn / vel_safe, 1e-38f);   // precise div (sensitive)
        float dt_exp = logf(ratio) * inv_a;             // precise log (sensitive)

        float dt_hit = small ? dt_lin : dt_exp;
        dt_hit = (vel == 0.0f || dt_hit < 0.0f) ? INF : dt_hit;

        float dt    = fminf(t, dt_hit);
        float x_lin = xc + vel * dt;
        float boa   = bc * inv_a;
        float x_exp = (xc + boa) * __expf(ac * dt) - boa;
        float x_new = small ? x_lin : x_exp;

        bool hit = dt_hit <= t;
        x_new = hit ? (xb + ((vel >= 0.0f) ? 1e-8f : -1e-8f)) : x_new;

        xc = fminf(fmaxf(x_new, 0.0f), 1.0f);
        t  = fmaxf(t - dt, 0.0f);
        ld += ac * dt;
        if (t <= 0.0f) break;
    }
    return make_float2(xc, ld);
}

__global__ void __launch_bounds__(NT)
cpab_ar_kernel(const float* __restrict__ x,
               const float* __restrict__ ip,
               const float* __restrict__ W0,
               const float* __restrict__ b0,
               const float* __restrict__ Wh,
               const float* __restrict__ bh,
               const float* __restrict__ Wo,
               const float* __restrict__ bo,
               float* __restrict__ out,
               int B)
{
    __shared__ Smem sm;
    const int tid = threadIdx.x;

    // ---- cooperative fill of packed weight cache (verbatim R12) ----
    for (int idx = tid; idx < 15 * 15 * 5; idx += NT) {
        int i = idx / 75, r = idx % 75, j = r / 5, p = r % 5;
        const float* s = W0 + (i * 15 + j) * 10 + 2 * p;
        sm.W0[i][j][p] = make_float2(s[0], s[1]);
    }
    for (int idx = tid; idx < 15 * 5; idx += NT) {
        int i = idx / 5, p = idx % 5;
        const float* s = b0 + i * 10 + 2 * p;
        sm.B0[i][p] = make_float2(s[0], s[1]);
    }
    for (int idx = tid; idx < 15 * 3 * 10 * 5; idx += NT) {
        int i = idx / 150, r = idx % 150, l = r / 50, r2 = r % 50, j = r2 / 5, p = r2 % 5;
        const float* s = Wh + ((i * 3 + l) * 10 + j) * 10 + 2 * p;
        sm.WH[i][l][j][p] = make_float2(s[0], s[1]);
    }
    for (int idx = tid; idx < 15 * 3 * 5; idx += NT) {
        int i = idx / 15, r = idx % 15, l = r / 5, p = r % 5;
        const float* s = bh + (i * 3 + l) * 10 + 2 * p;
        sm.BH[i][l][p] = make_float2(s[0], s[1]);
    }
    for (int idx = tid; idx < 15 * 10 * 5; idx += NT) {
        int i = idx / 50, r = idx % 50, j = r / 5, p = r % 5;
        const float* s = Wo + (i * 10 + j) * 9;
        sm.WO[i][j][p] = (p < 4) ? make_float2(s[2 * p], s[2 * p + 1])
                                 : make_float2(s[8], 0.0f);
    }
    for (int idx = tid; idx < 15 * 5; idx += NT) {
        int i = idx / 5, p = idx % 5;
        const float* s = bo + i * 9;
        sm.BO[i][p] = (p < 4) ? make_float2(s[2 * p], s[2 * p + 1])
                              : make_float2(s[8], 0.0f);
    }
    if (tid < 9) sm.IP[tid] = ip[tid];
    __syncthreads();

    const int n = blockIdx.x * NT + tid;
    if (n >= B) return;

    // ---- load + clip x (vectorized) ----
    float xr[16];
    {
        const float4* xg = reinterpret_cast<const float4*>(x + (size_t)n * 16);
        float4 v0 = xg[0], v1 = xg[1], v2 = xg[2], v3 = xg[3];
        float tmp[16] = { v0.x, v0.y, v0.z, v0.w,  v1.x, v1.y, v1.z, v1.w,
                          v2.x, v2.y, v2.z, v2.w,  v3.x, v3.y, v3.z, v3.w };
        const float lo = 1e-7f;
        const float hi = 1.0f - 1e-7f;
        #pragma unroll
        for (int k = 0; k < 16; ++k) xr[k] = fminf(fmaxf(tmp[k], lo), hi);
    }

    float zo[16], lo_[16];
    float* vb = &sm.V[0][tid];

    // ---- d = 0 transform: shared init_param ----
    vb[0] = 0.0f;
    #pragma unroll
    for (int k = 0; k < 9; ++k) vb[(k + 1) * NT] = sm.IP[k];
    vb[10 * NT] = 0.0f;
    {
        float2 r = cpab1(xr[0], vb);
        zo[0] = r.x; lo_[0] = r.y;
    }

    // ---- heads i = 0..14: MLP_i(x[0..i]) -> theta -> transform on x[i+1] ----
    for (int i = 0; i < 15; ++i) {
        float2 h[5];
        #pragma unroll
        for (int p = 0; p < 5; ++p) h[p] = sm.B0[i][p];

        // layer 0 (masked: only inputs 0..i contribute)
        for (int j = 0; j <= i; ++j) {
            float xv = xr[j];
            float2 xp = make_float2(xv, xv);
            #pragma unroll
            for (int p = 0; p < 5; ++p) h[p] = f2fma(xp, sm.W0[i][j][p], h[p]);
        }

        // 3 hidden layers with ReLU
        #pragma unroll
        for (int l = 0; l < 3; ++l) {
            float hs[10];
            #pragma unroll
            for (int p = 0; p < 5; ++p) { hs[2 * p] = h[p].x; hs[2 * p + 1] = h[p].y; }
            float2 g[5];
            #pragma unroll
            for (int p = 0; p < 5; ++p) g[p] = sm.BH[i][l][p];
            #pragma unroll
            for (int j = 0; j < 10; ++j) {
                float2 hp = make_float2(hs[j], hs[j]);
                #pragma unroll
                for (int p = 0; p < 5; ++p) g[p] = f2fma(hp, sm.WH[i][l][j][p], g[p]);
            }
            #pragma unroll
            for (int p = 0; p < 5; ++p) {
                h[p].x = fmaxf(g[p].x, 0.0f);
                h[p].y = fmaxf(g[p].y, 0.0f);
            }
        }

        // output layer (9 outputs, padded to 5 pairs)
        float hs[10];
        #pragma unroll
        for (int p = 0; p < 5; ++p) { hs[2 * p] = h[p].x; hs[2 * p + 1] = h[p].y; }
        float2 o[5];
        #pragma unroll
        for (int p = 0; p < 5; ++p) o[p] = sm.BO[i][p];
        #pragma unroll
        for (int j = 0; j < 10; ++j) {
            float2 hp = make_float2(hs[j], hs[j]);
            #pragma unroll
            for (int p = 0; p < 5; ++p) o[p] = f2fma(hp, sm.WO[i][j][p], o[p]);
        }

        // knot velocities v = [0, theta(9), 0]
        vb[0]      = 0.0f;
        vb[1 * NT] = o[0].x;  vb[2 * NT] = o[0].y;
        vb[3 * NT] = o[1].x;  vb[4 * NT] = o[1].y;
        vb[5 * NT] = o[2].x;  vb[6 * NT] = o[2].y;
        vb[7 * NT] = o[3].x;  vb[8 * NT] = o[3].y;
        vb[9 * NT] = o[4].x;
        vb[10 * NT] = 0.0f;

        float2 r = cpab1(xr[i + 1], vb);
        zo[i + 1] = r.x; lo_[i + 1] = r.y;
    }

    // ---- vectorized stores: z at [0, B*16), log-grad at [B*16, 2*B*16) ----
    float4* zg = reinterpret_cast<float4*>(out + (size_t)n * 16);
    float4* lg = reinterpret_cast<float4*>(out + (size_t)B * 16 + (size_t)n * 16);
    #pragma unroll
    for (int q = 0; q < 4; ++q) {
        zg[q] = make_float4(zo[4 * q], zo[4 * q + 1], zo[4 * q + 2], zo[4 * q + 3]);
        lg[q] = make_float4(lo_[4 * q], lo_[4 * q + 1], lo_[4 * q + 2], lo_[4 * q + 3]);
    }
}

extern "C" void kernel_launch(void* const* d_in, const int* in_sizes, int n_in,
                              void* d_out, int out_size)
{
    const float* x  = (const float*)d_in[0];
    const float* ip = (const float*)d_in[1];
    const float* W0 = (const float*)d_in[2];
    const float* b0 = (const float*)d_in[3];
    const float* Wh = (const float*)d_in[4];
    const float* bh = (const float*)d_in[5];
    const float* Wo = (const float*)d_in[6];
    const float* bo = (const float*)d_in[7];
    float* out = (float*)d_out;

    int B = in_sizes[0] / 16;
    int grid = (B + NT - 1) / NT;
    cpab_ar_kernel<<<grid, NT>>>(x, ip, W0, b0, Wh, bh, Wo, bo, out, B);
}